// round 5
// baseline (speedup 1.0000x reference)
#include <cuda_runtime.h>

// SparseEmbedding: out[b, :] = sum_n vals[b,n] * kernel[idx[b,n], :] + bias
// BATCH=4096, NNZ=32, VOCAB=1e6, DIM=64. float32 everywhere, idx int32.
//
// R4: sm_103a only allows .L2::evict_last on 256-bit loads, so gathers are
// restructured as LDG.E.256: each 8-lane group services one nnz row (32B per
// lane), 4 nnz per load step. evict_last keeps the ~31MB touched-row working
// set resident in the 126MB L2 across graph replays; idx/vals/out traffic is
// kept low-priority (.cs stores) so it doesn't displace table lines.

#define BATCH 4096
#define NNZ   32
#define DIM   64

struct F8 { float v[8]; };

__device__ __forceinline__ F8 ldg256_evict_last(const float* p) {
    F8 r;
    unsigned a0, a1, a2, a3, a4, a5, a6, a7;
    asm volatile(
        "ld.global.nc.L2::evict_last.v8.b32 {%0,%1,%2,%3,%4,%5,%6,%7}, [%8];"
        : "=r"(a0), "=r"(a1), "=r"(a2), "=r"(a3),
          "=r"(a4), "=r"(a5), "=r"(a6), "=r"(a7)
        : "l"(p));
    r.v[0] = __uint_as_float(a0); r.v[1] = __uint_as_float(a1);
    r.v[2] = __uint_as_float(a2); r.v[3] = __uint_as_float(a3);
    r.v[4] = __uint_as_float(a4); r.v[5] = __uint_as_float(a5);
    r.v[6] = __uint_as_float(a6); r.v[7] = __uint_as_float(a7);
    return r;
}

__global__ void __launch_bounds__(128, 1) sparse_embedding_kernel(
    const int*   __restrict__ idx,
    const float* __restrict__ vals,
    const float* __restrict__ table,
    const float* __restrict__ bias,
    float*       __restrict__ out)
{
    const int gwarp = (blockIdx.x * blockDim.x + threadIdx.x) >> 5;
    const int lane  = threadIdx.x & 31;
    if (gwarp >= BATCH) return;

    const int grp = lane >> 3;   // 0..3: which nnz within a step
    const int sub = lane & 7;    // owns dims [8*sub, 8*sub+8)

    // Each lane holds one (idx, val) pair for this row; broadcast via shfl.
    const int   my_idx = idx[gwarp * NNZ + lane];
    const float my_val = vals[gwarp * NNZ + lane];

    float acc[8] = {0, 0, 0, 0, 0, 0, 0, 0};

#pragma unroll
    for (int n = 0; n < NNZ; n += 4) {
        const int   id = __shfl_sync(0xffffffffu, my_idx, n + grp);
        const float v  = __shfl_sync(0xffffffffu, my_val, n + grp);
        const F8 kv = ldg256_evict_last(table + (size_t)id * DIM + sub * 8);
#pragma unroll
        for (int i = 0; i < 8; ++i)
            acc[i] = fmaf(v, kv.v[i], acc[i]);
    }

    // Merge the 4 nnz groups: lanes {l, l^8, l^16, l^24} hold the same dims.
#pragma unroll
    for (int i = 0; i < 8; ++i) {
        acc[i] += __shfl_xor_sync(0xffffffffu, acc[i], 8);
        acc[i] += __shfl_xor_sync(0xffffffffu, acc[i], 16);
    }

    if (grp == 0) {
        const float4 b0 = reinterpret_cast<const float4*>(bias)[sub * 2 + 0];
        const float4 b1 = reinterpret_cast<const float4*>(bias)[sub * 2 + 1];
        float* op = out + (size_t)gwarp * DIM + sub * 8;
        asm volatile("st.global.cs.v4.f32 [%0], {%1, %2, %3, %4};"
                     :: "l"(op),
                        "f"(acc[0] + b0.x), "f"(acc[1] + b0.y),
                        "f"(acc[2] + b0.z), "f"(acc[3] + b0.w));
        asm volatile("st.global.cs.v4.f32 [%0], {%1, %2, %3, %4};"
                     :: "l"(op + 4),
                        "f"(acc[4] + b1.x), "f"(acc[5] + b1.y),
                        "f"(acc[6] + b1.z), "f"(acc[7] + b1.w));
    }
}

extern "C" void kernel_launch(void* const* d_in, const int* in_sizes, int n_in,
                              void* d_out, int out_size)
{
    const int*   idx   = (const int*)  d_in[0];
    const float* vals  = (const float*)d_in[1];
    const float* table = (const float*)d_in[2];
    const float* bias  = (const float*)d_in[3];
    float*       out   = (float*)d_out;

    const int threads = 128;
    const int blocks  = (BATCH * 32) / threads;  // 1024 blocks, 1 warp/row
    sparse_embedding_kernel<<<blocks, threads>>>(idx, vals, table, bias, out);
}

// round 6
// speedup vs baseline: 1.0258x; 1.0258x over previous
#include <cuda_runtime.h>

// SparseEmbedding: out[b, :] = sum_n vals[b,n] * kernel[idx[b,n], :] + bias
// BATCH=4096, NNZ=32, VOCAB=1e6, DIM=64. float32 everywhere, idx int32.
//
// R5: all LDG-based variants plateau at ~3.2TB/s with nothing saturated in
// ncu -> per-SM outstanding-miss cap (~248 lines ~ 31.7KB in flight/SM).
// cp.async (LDGSTS) has NO observed outstanding-depth cap on B300 and lands
// in SMEM directly (.cg bypasses L1). Each warp gathers its 32 rows (8KB)
// via 16 LDGSTS.16 instructions, waits, then reduces from SMEM.

#define BATCH 4096
#define NNZ   32
#define DIM   64
#define WARPS_PER_CTA 4
#define ROW_BYTES (DIM * 4)           // 256B per table row
#define ROW_FLOATS (DIM)

__device__ __forceinline__ void cp_async16(void* smem_dst, const void* gmem_src) {
    unsigned saddr = (unsigned)__cvta_generic_to_shared(smem_dst);
    asm volatile("cp.async.cg.shared.global [%0], [%1], 16;"
                 :: "r"(saddr), "l"(gmem_src));
}

__global__ void __launch_bounds__(WARPS_PER_CTA * 32) sparse_embedding_kernel(
    const int*   __restrict__ idx,
    const float* __restrict__ vals,
    const float* __restrict__ table,
    const float* __restrict__ bias,
    float*       __restrict__ out)
{
    // One 2048-float (8KB) staging buffer per warp: 32 gathered rows.
    __shared__ float buf[WARPS_PER_CTA][NNZ * ROW_FLOATS];

    const int warp  = threadIdx.x >> 5;
    const int lane  = threadIdx.x & 31;
    const int gwarp = blockIdx.x * WARPS_PER_CTA + warp;   // batch row

    // Each lane holds one (idx, val) pair for this row; broadcast via shfl.
    const int   my_idx = idx[gwarp * NNZ + lane];
    const float my_val = vals[gwarp * NNZ + lane];

    // Phase 1: async-gather all 32 rows into SMEM.
    // Instr i copies 16B of row n = 2i + (lane>>4); lanes 0-15 cover row 2i,
    // lanes 16-31 cover row 2i+1. dst = buf + i*512B + lane*16B (contiguous).
    const int hi  = lane >> 4;        // which of the two rows this lane serves
    const int sub = lane & 15;        // 16B chunk within the 256B row
#pragma unroll
    for (int i = 0; i < NNZ / 2; ++i) {
        const int n  = 2 * i + hi;
        const int id = __shfl_sync(0xffffffffu, my_idx, n);
        const float* src = table + (size_t)id * DIM + sub * 4;
        float* dst = &buf[warp][n * ROW_FLOATS + sub * 4];
        cp_async16(dst, src);
    }
    asm volatile("cp.async.commit_group;" ::: "memory");
    asm volatile("cp.async.wait_group 0;" ::: "memory");
    __syncthreads();   // make all lanes' async copies visible

    // Phase 2: reduce from SMEM. Lane l owns dims [2l, 2l+1].
    float2 acc = reinterpret_cast<const float2*>(bias)[lane];
#pragma unroll
    for (int n = 0; n < NNZ; ++n) {
        const float v = __shfl_sync(0xffffffffu, my_val, n);
        const float2 kv = *reinterpret_cast<const float2*>(
            &buf[warp][n * ROW_FLOATS + lane * 2]);
        acc.x = fmaf(v, kv.x, acc.x);
        acc.y = fmaf(v, kv.y, acc.y);
    }

    reinterpret_cast<float2*>(out + (size_t)gwarp * DIM)[lane] = acc;
}

extern "C" void kernel_launch(void* const* d_in, const int* in_sizes, int n_in,
                              void* d_out, int out_size)
{
    const int*   idx   = (const int*)  d_in[0];
    const float* vals  = (const float*)d_in[1];
    const float* table = (const float*)d_in[2];
    const float* bias  = (const float*)d_in[3];
    float*       out   = (float*)d_out;

    const int threads = WARPS_PER_CTA * 32;          // 128
    const int blocks  = BATCH / WARPS_PER_CTA;       // 1024
    sparse_embedding_kernel<<<blocks, threads>>>(idx, vals, table, bias, out);
}